// round 16
// baseline (speedup 1.0000x reference)
#include <cuda_runtime.h>
#include <cuda_bf16.h>
#include <cstdint>

#define BB 8192
#define LL 256
#define NBUF 4
#define ROWB 144                      // 9 granules * 16B
#define WARP_BUF (32 * ROWB)          // 4608 B
#define WARP_SMEM (NBUF * WARP_BUF)   // 18432 B
#define DYN_SMEM (4 * WARP_SMEM)      // 73728 B

static __device__ __forceinline__ unsigned long long pk2(float lo, float hi) {
    unsigned long long r; asm("mov.b64 %0, {%1,%2};" : "=l"(r) : "f"(lo), "f"(hi)); return r;
}
static __device__ __forceinline__ void upk2(float& lo, float& hi, unsigned long long v) {
    asm("mov.b64 {%0,%1}, %2;" : "=f"(lo), "=f"(hi) : "l"(v));
}
static __device__ __forceinline__ unsigned long long fma2_(unsigned long long a, unsigned long long b, unsigned long long c) {
    unsigned long long d; asm("fma.rn.f32x2 %0, %1, %2, %3;" : "=l"(d) : "l"(a), "l"(b), "l"(c)); return d;
}
static __device__ __forceinline__ unsigned long long mul2_(unsigned long long a, unsigned long long b) {
    unsigned long long d; asm("mul.rn.f32x2 %0, %1, %2;" : "=l"(d) : "l"(a), "l"(b)); return d;
}
static __device__ __forceinline__ unsigned long long add2_(unsigned long long a, unsigned long long b) {
    unsigned long long d; asm("add.rn.f32x2 %0, %1, %2;" : "=l"(d) : "l"(a), "l"(b)); return d;
}
static __device__ __forceinline__ unsigned int smem_u32(const void* p) {
    unsigned int a; asm("{ .reg .u64 t; cvta.to.shared.u64 t, %1; cvt.u32.u64 %0, t; }" : "=r"(a) : "l"(p)); return a;
}
static __device__ __forceinline__ void cpasync16(unsigned int dst, const void* src) {
    asm volatile("cp.async.ca.shared.global [%0], [%1], 16;" :: "r"(dst), "l"(src));
}
static __device__ __forceinline__ float lds_f(unsigned int a) {
    float v; asm volatile("ld.shared.f32 %0, [%1];" : "=f"(v) : "r"(a)); return v;
}
#define CP_COMMIT() asm volatile("cp.async.commit_group;" ::: "memory")
#define CP_WAIT(n)  asm volatile("cp.async.wait_group %0;" :: "n"(n) : "memory")

__global__ __launch_bounds__(128) void crf_fwd_kernel(
    const float* __restrict__ inputs,   // [B, L, 9]
    const int*   __restrict__ path,     // [B, L]
    const float* __restrict__ tran,     // [9, 9]
    const float* __restrict__ initv,    // [9]
    float* __restrict__ out)            // [B]
{
    __shared__ float s_tran[81];
    __shared__ float s_init[9];
    __shared__ float fin[64][26];
    extern __shared__ __align__(16) char xbuf[];   // DYN_SMEM bytes

    const int tid  = threadIdx.x;
    const int w    = tid >> 5;
    const int lane = tid & 31;
    const int dir  = w & 1;              // 0 = fwd (t 0..127), 1 = bwd (t 255..128)
    const int half = w >> 1;             // 0,1 : which 32-batch subset
    const int b    = blockIdx.x * 64 + half * 32 + lane;
    const int frow = half * 32 + lane;

    for (int i = tid; i < 81; i += 128) s_tran[i] = tran[i];
    if (tid < 9) s_init[tid] = initv[tid];
    __syncthreads();

    // E packs per lane. fwd: M[s][o] = exp(tran[s][o]); bwd: M[s][o] = exp(tran[o][s]).
    unsigned long long Epk[9][4];
    float Ek8[9];
    #pragma unroll
    for (int k = 0; k < 9; ++k) {
        float e[9];
        #pragma unroll
        for (int o = 0; o < 9; ++o)
            e[o] = __expf(dir ? s_tran[o * 9 + k] : s_tran[k * 9 + o]);
        Epk[k][0] = pk2(e[0], e[1]); Epk[k][1] = pk2(e[2], e[3]);
        Epk[k][2] = pk2(e[4], e[5]); Epk[k][3] = pk2(e[6], e[7]);
        Ek8[k] = e[8];
    }

    // cp.async: 32 batches x 9 granules = 288 float4 per group -> exactly 9 per lane
    const unsigned int wbase = smem_u32(xbuf) + (unsigned int)w * WARP_SMEM;
    const char* gsrc[9];
    unsigned int sdst[9];
    #pragma unroll
    for (int i = 0; i < 9; ++i) {
        int f4 = lane + 32 * i;
        int bi = f4 / 9, oi = f4 - bi * 9;
        gsrc[i] = (const char*)inputs
                + (size_t)(blockIdx.x * 64 + half * 32 + bi) * (LL * 9 * 4) + oi * 16;
        sdst[i] = wbase + (unsigned int)(bi * ROWB + oi * 16);
    }
    auto issue = [&](int g) {
        unsigned int boff = (unsigned int)(g & 3) * WARP_BUF;
        #pragma unroll
        for (int i = 0; i < 9; ++i)
            cpasync16(sdst[i] + boff, gsrc[i] + (size_t)g * 144);
        CP_COMMIT();
    };

    const unsigned int myrow = wbase + (unsigned int)lane * ROWB;
    float4 X[9];
    auto loadX = [&](int g) {
        unsigned int a = myrow + (unsigned int)(g & 3) * WARP_BUF;
        #pragma unroll
        for (int i = 0; i < 9; ++i)
            asm volatile("ld.shared.v4.f32 {%0,%1,%2,%3}, [%4];"
                         : "=f"(X[i].x), "=f"(X[i].y), "=f"(X[i].z), "=f"(X[i].w)
                         : "r"(a + i * 16));
    };

    const int4* pb4 = (const int4*)(path + (size_t)b * LL);

    float p0,p1,p2,p3,p4,p5,p6,p7,p8;
    float C = 0.f, emit = 0.f, tracc = 0.f;
    int ptp;

    auto matvec = [&](float y0, float y1, float y2, float y3, float y4,
                      float y5, float y6, float y7, float y8,
                      float& n0, float& n1, float& n2, float& n3, float& n4,
                      float& n5, float& n6, float& n7, float& n8) {
        unsigned long long q, A0, A1, A2, A3, B0, B1, B2, B3;
        float a8, b8;
        q = pk2(y0,y0);
        A0 = mul2_(q, Epk[0][0]); A1 = mul2_(q, Epk[0][1]);
        A2 = mul2_(q, Epk[0][2]); A3 = mul2_(q, Epk[0][3]);
        a8 = y0 * Ek8[0];
        q = pk2(y1,y1);
        A0 = fma2_(q, Epk[1][0], A0); A1 = fma2_(q, Epk[1][1], A1);
        A2 = fma2_(q, Epk[1][2], A2); A3 = fma2_(q, Epk[1][3], A3);
        a8 = fmaf(y1, Ek8[1], a8);
        q = pk2(y2,y2);
        A0 = fma2_(q, Epk[2][0], A0); A1 = fma2_(q, Epk[2][1], A1);
        A2 = fma2_(q, Epk[2][2], A2); A3 = fma2_(q, Epk[2][3], A3);
        a8 = fmaf(y2, Ek8[2], a8);
        q = pk2(y3,y3);
        A0 = fma2_(q, Epk[3][0], A0); A1 = fma2_(q, Epk[3][1], A1);
        A2 = fma2_(q, Epk[3][2], A2); A3 = fma2_(q, Epk[3][3], A3);
        a8 = fmaf(y3, Ek8[3], a8);
        q = pk2(y4,y4);
        B0 = mul2_(q, Epk[4][0]); B1 = mul2_(q, Epk[4][1]);
        B2 = mul2_(q, Epk[4][2]); B3 = mul2_(q, Epk[4][3]);
        b8 = y4 * Ek8[4];
        q = pk2(y5,y5);
        B0 = fma2_(q, Epk[5][0], B0); B1 = fma2_(q, Epk[5][1], B1);
        B2 = fma2_(q, Epk[5][2], B2); B3 = fma2_(q, Epk[5][3], B3);
        b8 = fmaf(y5, Ek8[5], b8);
        q = pk2(y6,y6);
        B0 = fma2_(q, Epk[6][0], B0); B1 = fma2_(q, Epk[6][1], B1);
        B2 = fma2_(q, Epk[6][2], B2); B3 = fma2_(q, Epk[6][3], B3);
        b8 = fmaf(y6, Ek8[6], b8);
        q = pk2(y7,y7);
        B0 = fma2_(q, Epk[7][0], B0); B1 = fma2_(q, Epk[7][1], B1);
        B2 = fma2_(q, Epk[7][2], B2); B3 = fma2_(q, Epk[7][3], B3);
        b8 = fmaf(y7, Ek8[7], b8);
        q = pk2(y8,y8);
        B0 = fma2_(q, Epk[8][0], B0); B1 = fma2_(q, Epk[8][1], B1);
        B2 = fma2_(q, Epk[8][2], B2); B3 = fma2_(q, Epk[8][3], B3);
        b8 = fmaf(y8, Ek8[8], b8);
        A0 = add2_(A0, B0); A1 = add2_(A1, B1);
        A2 = add2_(A2, B2); A3 = add2_(A3, B3);
        a8 += b8;
        upk2(n0, n1, A0); upk2(n2, n3, A1);
        upk2(n4, n5, A2); upk2(n6, n7, A3);
        n8 = a8;
    };

    auto stepf = [&](const float* e, unsigned int xb_t, int pt) {
        float n0,n1,n2,n3,n4,n5,n6,n7,n8;
        matvec(p0,p1,p2,p3,p4,p5,p6,p7,p8, n0,n1,n2,n3,n4,n5,n6,n7,n8);
        p0=n0*e[0]; p1=n1*e[1]; p2=n2*e[2]; p3=n3*e[3]; p4=n4*e[4];
        p5=n5*e[5]; p6=n6*e[6]; p7=n7*e[7]; p8=n8*e[8];
        emit  += lds_f(xb_t + (unsigned int)(pt * 4));
        tracc += s_tran[ptp * 9 + pt];
        ptp = pt;
    };
    auto stepb = [&](const float* e, unsigned int xb_t, int pt) {
        float y0=p0*e[0], y1=p1*e[1], y2=p2*e[2], y3=p3*e[3], y4=p4*e[4];
        float y5=p5*e[5], y6=p6*e[6], y7=p7*e[7], y8=p8*e[8];
        matvec(y0,y1,y2,y3,y4,y5,y6,y7,y8, p0,p1,p2,p3,p4,p5,p6,p7,p8);
        emit  += lds_f(xb_t + (unsigned int)(pt * 4));
        tracc += s_tran[pt * 9 + ptp];
        ptp = pt;
    };

    auto renorm = [&]() {
        float s = (((p0+p1)+(p2+p3)) + ((p4+p5)+(p6+p7))) + p8;
        C += __logf(s);
        float inv = __fdividef(1.f, s);
        p0*=inv; p1*=inv; p2*=inv; p3*=inv; p4*=inv;
        p5*=inv; p6*=inv; p7*=inv; p8*=inv;
    };

    float ex[36];
    auto expX = [&]() {
        #pragma unroll
        for (int i = 0; i < 9; ++i) {
            ex[4*i+0] = __expf(X[i].x); ex[4*i+1] = __expf(X[i].y);
            ex[4*i+2] = __expf(X[i].z); ex[4*i+3] = __expf(X[i].w);
        }
    };

    if (dir == 0) {
        // ===== forward: groups 0..31 (t = 0..127) =====
        auto fbody = [&](int g) {
            loadX(g);
            expX();
            int4 P = pb4[g];
            unsigned int xb = myrow + (unsigned int)(g & 3) * WARP_BUF;
            stepf(ex + 0,  xb,       P.x);
            stepf(ex + 9,  xb + 36,  P.y);
            stepf(ex + 18, xb + 72,  P.z);
            stepf(ex + 27, xb + 108, P.w);
            if (g & 1) renorm();
        };

        issue(0); issue(1); issue(2);
        float initterm = 0.f;

        // g = 0: init + 3 steps
        CP_WAIT(2); __syncwarp();
        issue(3);
        loadX(0);
        expX();
        {
            int4 P = pb4[0];
            unsigned int xb = myrow;
            p0 = __expf(s_init[0]) * ex[0];
            p1 = __expf(s_init[1]) * ex[1];
            p2 = __expf(s_init[2]) * ex[2];
            p3 = __expf(s_init[3]) * ex[3];
            p4 = __expf(s_init[4]) * ex[4];
            p5 = __expf(s_init[5]) * ex[5];
            p6 = __expf(s_init[6]) * ex[6];
            p7 = __expf(s_init[7]) * ex[7];
            p8 = __expf(s_init[8]) * ex[8];
            ptp = P.x;
            emit = lds_f(xb + (unsigned int)(P.x * 4));
            initterm = s_init[P.x];
            stepf(ex + 9,  xb + 36,  P.y);
            stepf(ex + 18, xb + 72,  P.z);
            stepf(ex + 27, xb + 108, P.w);
        }

        #pragma unroll 1
        for (int g = 1; g <= 28; ++g) {
            CP_WAIT(2); __syncwarp();
            issue(g + 3);
            fbody(g);
        }
        // pipeline drain: descending waits (tail-race fix)
        CP_WAIT(2); __syncwarp(); fbody(29);
        CP_WAIT(1); __syncwarp(); fbody(30);
        CP_WAIT(0); __syncwarp(); fbody(31);

        fin[frow][0]=p0; fin[frow][1]=p1; fin[frow][2]=p2; fin[frow][3]=p3;
        fin[frow][4]=p4; fin[frow][5]=p5; fin[frow][6]=p6; fin[frow][7]=p7;
        fin[frow][8]=p8;
        fin[frow][9]  = C;
        fin[frow][10] = emit + initterm + tracc;
        fin[frow][11] = __int_as_float(ptp);
    } else {
        // ===== backward: groups 63..32 (t = 255..128) =====
        auto bbody = [&](int g) {
            loadX(g);
            expX();
            int4 P = pb4[g];
            unsigned int xb = myrow + (unsigned int)(g & 3) * WARP_BUF;
            stepb(ex + 27, xb + 108, P.w);
            stepb(ex + 18, xb + 72,  P.z);
            stepb(ex + 9,  xb + 36,  P.y);
            stepb(ex + 0,  xb,       P.x);
            if ((g & 1) == 0) renorm();
        };

        issue(63); issue(62); issue(61);

        // g = 63: init + 3 steps
        CP_WAIT(2); __syncwarp();
        issue(60);
        loadX(63);
        expX();
        {
            int4 P = pb4[63];
            unsigned int xb = myrow + 3u * WARP_BUF;
            // init: p = E * exp(x_255) = beta_254
            matvec(ex[27],ex[28],ex[29],ex[30],ex[31],ex[32],ex[33],ex[34],ex[35],
                   p0,p1,p2,p3,p4,p5,p6,p7,p8);
            ptp = P.w;
            emit = lds_f(xb + 108 + (unsigned int)(P.w * 4));
            stepb(ex + 18, xb + 72, P.z);
            stepb(ex + 9,  xb + 36, P.y);
            stepb(ex + 0,  xb,      P.x);
        }

        #pragma unroll 1
        for (int g = 62; g >= 35; --g) {
            CP_WAIT(2); __syncwarp();
            issue(g - 3);
            bbody(g);
        }
        // pipeline drain: descending waits
        CP_WAIT(2); __syncwarp(); bbody(34);
        CP_WAIT(1); __syncwarp(); bbody(33);
        CP_WAIT(0); __syncwarp(); bbody(32);

        fin[frow][12]=p0; fin[frow][13]=p1; fin[frow][14]=p2; fin[frow][15]=p3;
        fin[frow][16]=p4; fin[frow][17]=p5; fin[frow][18]=p6; fin[frow][19]=p7;
        fin[frow][20]=p8;
        fin[frow][21] = C;
        fin[frow][22] = emit + tracc;
        fin[frow][23] = __int_as_float(ptp);
    }

    __syncthreads();

    if (dir == 0) {
        float dot = 0.f;
        #pragma unroll
        for (int i = 0; i < 9; ++i)
            dot = fmaf(fin[frow][i], fin[frow][12 + i], dot);
        float logZ = fin[frow][9] + fin[frow][21] + __logf(dot);
        int pa = __float_as_int(fin[frow][11]);
        int pb = __float_as_int(fin[frow][23]);
        float score = fin[frow][10] + fin[frow][22] + s_tran[pa * 9 + pb];
        out[b] = logZ - score;
    }
}

extern "C" void kernel_launch(void* const* d_in, const int* in_sizes, int n_in,
                              void* d_out, int out_size) {
    (void)in_sizes; (void)n_in; (void)out_size;
    const float* inputs = (const float*)d_in[0];
    const int*   path   = (const int*)d_in[1];
    const float* tran   = (const float*)d_in[2];
    const float* initv  = (const float*)d_in[3];
    float* out = (float*)d_out;

    cudaFuncSetAttribute(crf_fwd_kernel,
                         cudaFuncAttributeMaxDynamicSharedMemorySize, DYN_SMEM);
    crf_fwd_kernel<<<BB / 64, 128, DYN_SMEM>>>(inputs, path, tran, initv, out);
}

// round 17
// speedup vs baseline: 1.3148x; 1.3148x over previous
#include <cuda_runtime.h>
#include <cuda_bf16.h>
#include <cstdint>

#define BB 8192
#define LL 256
#define NBUF 4
#define ROWB 144                       // 9 granules * 16B, conflict-free LDS.128 stride
#define WARP_XBUF (32 * ROWB)          // 4608 B
#define WARP_XSMEM (NBUF * WARP_XBUF)  // 18432 B
#define X_TOTAL (4 * WARP_XSMEM)       // 73728 B
#define WARP_PBUF 512                  // 32 batches * 16 B path per group
#define WARP_PSMEM (NBUF * WARP_PBUF)  // 2048 B
#define DYN_SMEM (X_TOTAL + 4 * WARP_PSMEM)   // 81920 B

static __device__ __forceinline__ unsigned long long pk2(float lo, float hi) {
    unsigned long long r; asm("mov.b64 %0, {%1,%2};" : "=l"(r) : "f"(lo), "f"(hi)); return r;
}
static __device__ __forceinline__ void upk2(float& lo, float& hi, unsigned long long v) {
    asm("mov.b64 {%0,%1}, %2;" : "=f"(lo), "=f"(hi) : "l"(v));
}
static __device__ __forceinline__ unsigned long long fma2_(unsigned long long a, unsigned long long b, unsigned long long c) {
    unsigned long long d; asm("fma.rn.f32x2 %0, %1, %2, %3;" : "=l"(d) : "l"(a), "l"(b), "l"(c)); return d;
}
static __device__ __forceinline__ unsigned long long mul2_(unsigned long long a, unsigned long long b) {
    unsigned long long d; asm("mul.rn.f32x2 %0, %1, %2;" : "=l"(d) : "l"(a), "l"(b)); return d;
}
static __device__ __forceinline__ unsigned long long add2_(unsigned long long a, unsigned long long b) {
    unsigned long long d; asm("add.rn.f32x2 %0, %1, %2;" : "=l"(d) : "l"(a), "l"(b)); return d;
}
static __device__ __forceinline__ unsigned int smem_u32(const void* p) {
    unsigned int a; asm("{ .reg .u64 t; cvta.to.shared.u64 t, %1; cvt.u32.u64 %0, t; }" : "=r"(a) : "l"(p)); return a;
}
static __device__ __forceinline__ void cpasync16(unsigned int dst, const void* src) {
    asm volatile("cp.async.ca.shared.global [%0], [%1], 16;" :: "r"(dst), "l"(src));
}
static __device__ __forceinline__ float lds_f(unsigned int a) {
    float v; asm volatile("ld.shared.f32 %0, [%1];" : "=f"(v) : "r"(a)); return v;
}
#define CP_COMMIT() asm volatile("cp.async.commit_group;" ::: "memory")
#define CP_WAIT(n)  asm volatile("cp.async.wait_group %0;" :: "n"(n) : "memory")

__global__ __launch_bounds__(128) void crf_fwd_kernel(
    const float* __restrict__ inputs,   // [B, L, 9]
    const int*   __restrict__ path,     // [B, L]
    const float* __restrict__ tran,     // [9, 9]
    const float* __restrict__ initv,    // [9]
    float* __restrict__ out)            // [B]
{
    __shared__ float s_tran[81];
    __shared__ float s_init[9];
    __shared__ float fin[64][26];
    extern __shared__ __align__(16) char dynbuf[];

    const int tid  = threadIdx.x;
    const int w    = tid >> 5;
    const int lane = tid & 31;
    const int dir  = w & 1;              // 0 = fwd (t 0..127), 1 = bwd (t 255..128)
    const int half = w >> 1;
    const int b    = blockIdx.x * 64 + half * 32 + lane;
    const int frow = half * 32 + lane;

    for (int i = tid; i < 81; i += 128) s_tran[i] = tran[i];
    if (tid < 9) s_init[tid] = initv[tid];
    __syncthreads();

    // E packs per lane. fwd: M[s][o] = exp(tran[s][o]); bwd: M[s][o] = exp(tran[o][s]).
    unsigned long long Epk[9][4];
    float Ek8[9];
    #pragma unroll
    for (int k = 0; k < 9; ++k) {
        float e[9];
        #pragma unroll
        for (int o = 0; o < 9; ++o)
            e[o] = __expf(dir ? s_tran[o * 9 + k] : s_tran[k * 9 + o]);
        Epk[k][0] = pk2(e[0], e[1]); Epk[k][1] = pk2(e[2], e[3]);
        Epk[k][2] = pk2(e[4], e[5]); Epk[k][3] = pk2(e[6], e[7]);
        Ek8[k] = e[8];
    }

    // x staging: 32 batches x 9 granules = 288 float4 per group -> exactly 9 per lane
    const unsigned int xwbase = smem_u32(dynbuf) + (unsigned int)w * WARP_XSMEM;
    const unsigned int pwbase = smem_u32(dynbuf) + X_TOTAL + (unsigned int)w * WARP_PSMEM;
    const char* gsrc[9];
    unsigned int sdst[9];
    #pragma unroll
    for (int i = 0; i < 9; ++i) {
        int f4 = lane + 32 * i;
        int bi = f4 / 9, oi = f4 - bi * 9;
        gsrc[i] = (const char*)inputs
                + (size_t)(blockIdx.x * 64 + half * 32 + bi) * (LL * 9 * 4) + oi * 16;
        sdst[i] = xwbase + (unsigned int)(bi * ROWB + oi * 16);
    }
    const char* psrc = (const char*)(path + (size_t)b * LL);   // my batch's path row
    const unsigned int pdst = pwbase + (unsigned int)(lane * 16);

    auto issue = [&](int g) {
        unsigned int boff = (unsigned int)(g & 3) * WARP_XBUF;
        #pragma unroll
        for (int i = 0; i < 9; ++i)
            cpasync16(sdst[i] + boff, gsrc[i] + (size_t)g * 144);
        cpasync16(pdst + (unsigned int)(g & 3) * WARP_PBUF, psrc + (size_t)g * 16);
        CP_COMMIT();
    };

    const unsigned int myrow = xwbase + (unsigned int)lane * ROWB;
    float4 X[9];
    auto loadX = [&](int g) {
        unsigned int a = myrow + (unsigned int)(g & 3) * WARP_XBUF;
        #pragma unroll
        for (int i = 0; i < 9; ++i)
            asm volatile("ld.shared.v4.f32 {%0,%1,%2,%3}, [%4];"
                         : "=f"(X[i].x), "=f"(X[i].y), "=f"(X[i].z), "=f"(X[i].w)
                         : "r"(a + i * 16));
    };
    auto loadP = [&](int g) {
        int4 P;
        asm volatile("ld.shared.v4.u32 {%0,%1,%2,%3}, [%4];"
                     : "=r"(P.x), "=r"(P.y), "=r"(P.z), "=r"(P.w)
                     : "r"(pdst + (unsigned int)(g & 3) * WARP_PBUF));
        return P;
    };

    float p0,p1,p2,p3,p4,p5,p6,p7,p8;
    float C = 0.f, emit = 0.f, tracc = 0.f;
    int ptp;

    auto matvec = [&](float y0, float y1, float y2, float y3, float y4,
                      float y5, float y6, float y7, float y8,
                      float& n0, float& n1, float& n2, float& n3, float& n4,
                      float& n5, float& n6, float& n7, float& n8) {
        unsigned long long q, A0, A1, A2, A3, B0, B1, B2, B3;
        float a8, b8;
        q = pk2(y0,y0);
        A0 = mul2_(q, Epk[0][0]); A1 = mul2_(q, Epk[0][1]);
        A2 = mul2_(q, Epk[0][2]); A3 = mul2_(q, Epk[0][3]);
        a8 = y0 * Ek8[0];
        q = pk2(y1,y1);
        A0 = fma2_(q, Epk[1][0], A0); A1 = fma2_(q, Epk[1][1], A1);
        A2 = fma2_(q, Epk[1][2], A2); A3 = fma2_(q, Epk[1][3], A3);
        a8 = fmaf(y1, Ek8[1], a8);
        q = pk2(y2,y2);
        A0 = fma2_(q, Epk[2][0], A0); A1 = fma2_(q, Epk[2][1], A1);
        A2 = fma2_(q, Epk[2][2], A2); A3 = fma2_(q, Epk[2][3], A3);
        a8 = fmaf(y2, Ek8[2], a8);
        q = pk2(y3,y3);
        A0 = fma2_(q, Epk[3][0], A0); A1 = fma2_(q, Epk[3][1], A1);
        A2 = fma2_(q, Epk[3][2], A2); A3 = fma2_(q, Epk[3][3], A3);
        a8 = fmaf(y3, Ek8[3], a8);
        q = pk2(y4,y4);
        B0 = mul2_(q, Epk[4][0]); B1 = mul2_(q, Epk[4][1]);
        B2 = mul2_(q, Epk[4][2]); B3 = mul2_(q, Epk[4][3]);
        b8 = y4 * Ek8[4];
        q = pk2(y5,y5);
        B0 = fma2_(q, Epk[5][0], B0); B1 = fma2_(q, Epk[5][1], B1);
        B2 = fma2_(q, Epk[5][2], B2); B3 = fma2_(q, Epk[5][3], B3);
        b8 = fmaf(y5, Ek8[5], b8);
        q = pk2(y6,y6);
        B0 = fma2_(q, Epk[6][0], B0); B1 = fma2_(q, Epk[6][1], B1);
        B2 = fma2_(q, Epk[6][2], B2); B3 = fma2_(q, Epk[6][3], B3);
        b8 = fmaf(y6, Ek8[6], b8);
        q = pk2(y7,y7);
        B0 = fma2_(q, Epk[7][0], B0); B1 = fma2_(q, Epk[7][1], B1);
        B2 = fma2_(q, Epk[7][2], B2); B3 = fma2_(q, Epk[7][3], B3);
        b8 = fmaf(y7, Ek8[7], b8);
        q = pk2(y8,y8);
        B0 = fma2_(q, Epk[8][0], B0); B1 = fma2_(q, Epk[8][1], B1);
        B2 = fma2_(q, Epk[8][2], B2); B3 = fma2_(q, Epk[8][3], B3);
        b8 = fmaf(y8, Ek8[8], b8);
        A0 = add2_(A0, B0); A1 = add2_(A1, B1);
        A2 = add2_(A2, B2); A3 = add2_(A3, B3);
        a8 += b8;
        upk2(n0, n1, A0); upk2(n2, n3, A1);
        upk2(n4, n5, A2); upk2(n6, n7, A3);
        n8 = a8;
    };

    // pure scan steps (no bookkeeping inside)
    auto stepf = [&](float x0, float x1, float x2, float x3, float x4,
                     float x5, float x6, float x7, float x8) {
        float e0=__expf(x0), e1=__expf(x1), e2=__expf(x2), e3=__expf(x3), e4=__expf(x4);
        float e5=__expf(x5), e6=__expf(x6), e7=__expf(x7), e8=__expf(x8);
        float n0,n1,n2,n3,n4,n5,n6,n7,n8;
        matvec(p0,p1,p2,p3,p4,p5,p6,p7,p8, n0,n1,n2,n3,n4,n5,n6,n7,n8);
        p0=n0*e0; p1=n1*e1; p2=n2*e2; p3=n3*e3; p4=n4*e4;
        p5=n5*e5; p6=n6*e6; p7=n7*e7; p8=n8*e8;
    };
    auto stepb = [&](float x0, float x1, float x2, float x3, float x4,
                     float x5, float x6, float x7, float x8) {
        float y0=p0*__expf(x0), y1=p1*__expf(x1), y2=p2*__expf(x2);
        float y3=p3*__expf(x3), y4=p4*__expf(x4), y5=p5*__expf(x5);
        float y6=p6*__expf(x6), y7=p7*__expf(x7), y8=p8*__expf(x8);
        matvec(y0,y1,y2,y3,y4,y5,y6,y7,y8, p0,p1,p2,p3,p4,p5,p6,p7,p8);
    };

    auto renorm = [&]() {
        float s = (((p0+p1)+(p2+p3)) + ((p4+p5)+(p6+p7))) + p8;
        C += __logf(s);
        float inv = __fdividef(1.f, s);
        p0*=inv; p1*=inv; p2*=inv; p3*=inv; p4*=inv;
        p5*=inv; p6*=inv; p7*=inv; p8*=inv;
    };

    if (dir == 0) {
        // ===== forward: groups 0..31 (t = 0..127) =====
        auto fbody = [&](int g) {
            loadX(g);
            int4 P = loadP(g);
            unsigned int xb = myrow + (unsigned int)(g & 3) * WARP_XBUF;
            stepf(X[0].x,X[0].y,X[0].z,X[0].w, X[1].x,X[1].y,X[1].z,X[1].w, X[2].x);
            stepf(X[2].y,X[2].z,X[2].w, X[3].x,X[3].y,X[3].z,X[3].w, X[4].x,X[4].y);
            stepf(X[4].z,X[4].w, X[5].x,X[5].y,X[5].z,X[5].w, X[6].x,X[6].y,X[6].z);
            stepf(X[6].w, X[7].x,X[7].y,X[7].z,X[7].w, X[8].x,X[8].y,X[8].z,X[8].w);
            // batched bookkeeping (operands all resident/staged)
            emit += lds_f(xb + (unsigned int)(P.x * 4))
                  + lds_f(xb + 36 + (unsigned int)(P.y * 4))
                  + lds_f(xb + 72 + (unsigned int)(P.z * 4))
                  + lds_f(xb + 108 + (unsigned int)(P.w * 4));
            tracc += s_tran[ptp * 9 + P.x] + s_tran[P.x * 9 + P.y]
                   + s_tran[P.y * 9 + P.z] + s_tran[P.z * 9 + P.w];
            ptp = P.w;
            if (g & 1) renorm();
        };

        issue(0); issue(1); issue(2);
        float initterm = 0.f;

        // g = 0: init + 3 steps
        CP_WAIT(2); __syncwarp();
        issue(3);
        loadX(0);
        {
            int4 P = loadP(0);
            unsigned int xb = myrow;
            p0 = __expf(s_init[0] + X[0].x);
            p1 = __expf(s_init[1] + X[0].y);
            p2 = __expf(s_init[2] + X[0].z);
            p3 = __expf(s_init[3] + X[0].w);
            p4 = __expf(s_init[4] + X[1].x);
            p5 = __expf(s_init[5] + X[1].y);
            p6 = __expf(s_init[6] + X[1].z);
            p7 = __expf(s_init[7] + X[1].w);
            p8 = __expf(s_init[8] + X[2].x);
            stepf(X[2].y,X[2].z,X[2].w, X[3].x,X[3].y,X[3].z,X[3].w, X[4].x,X[4].y);
            stepf(X[4].z,X[4].w, X[5].x,X[5].y,X[5].z,X[5].w, X[6].x,X[6].y,X[6].z);
            stepf(X[6].w, X[7].x,X[7].y,X[7].z,X[7].w, X[8].x,X[8].y,X[8].z,X[8].w);
            emit = lds_f(xb + (unsigned int)(P.x * 4))
                 + lds_f(xb + 36 + (unsigned int)(P.y * 4))
                 + lds_f(xb + 72 + (unsigned int)(P.z * 4))
                 + lds_f(xb + 108 + (unsigned int)(P.w * 4));
            tracc = s_tran[P.x * 9 + P.y] + s_tran[P.y * 9 + P.z] + s_tran[P.z * 9 + P.w];
            initterm = s_init[P.x];
            ptp = P.w;
        }

        #pragma unroll 1
        for (int g = 1; g <= 28; ++g) {
            CP_WAIT(2); __syncwarp();
            issue(g + 3);
            fbody(g);
        }
        CP_WAIT(2); __syncwarp(); fbody(29);
        CP_WAIT(1); __syncwarp(); fbody(30);
        CP_WAIT(0); __syncwarp(); fbody(31);

        fin[frow][0]=p0; fin[frow][1]=p1; fin[frow][2]=p2; fin[frow][3]=p3;
        fin[frow][4]=p4; fin[frow][5]=p5; fin[frow][6]=p6; fin[frow][7]=p7;
        fin[frow][8]=p8;
        fin[frow][9]  = C;
        fin[frow][10] = emit + initterm + tracc;
        fin[frow][11] = __int_as_float(ptp);
    } else {
        // ===== backward: groups 63..32 (t = 255..128) =====
        auto bbody = [&](int g) {
            loadX(g);
            int4 P = loadP(g);
            unsigned int xb = myrow + (unsigned int)(g & 3) * WARP_XBUF;
            stepb(X[6].w, X[7].x,X[7].y,X[7].z,X[7].w, X[8].x,X[8].y,X[8].z,X[8].w);
            stepb(X[4].z,X[4].w, X[5].x,X[5].y,X[5].z,X[5].w, X[6].x,X[6].y,X[6].z);
            stepb(X[2].y,X[2].z,X[2].w, X[3].x,X[3].y,X[3].z,X[3].w, X[4].x,X[4].y);
            stepb(X[0].x,X[0].y,X[0].z,X[0].w, X[1].x,X[1].y,X[1].z,X[1].w, X[2].x);
            emit += lds_f(xb + (unsigned int)(P.x * 4))
                  + lds_f(xb + 36 + (unsigned int)(P.y * 4))
                  + lds_f(xb + 72 + (unsigned int)(P.z * 4))
                  + lds_f(xb + 108 + (unsigned int)(P.w * 4));
            tracc += s_tran[P.w * 9 + ptp] + s_tran[P.z * 9 + P.w]
                   + s_tran[P.y * 9 + P.z] + s_tran[P.x * 9 + P.y];
            ptp = P.x;
            if ((g & 1) == 0) renorm();
        };

        issue(63); issue(62); issue(61);

        // g = 63: init + 3 steps
        CP_WAIT(2); __syncwarp();
        issue(60);
        loadX(63);
        {
            int4 P = loadP(63);
            unsigned int xb = myrow + 3u * WARP_XBUF;
            // init: p = E * exp(x_255) = beta_254
            float y0=__expf(X[6].w), y1=__expf(X[7].x), y2=__expf(X[7].y);
            float y3=__expf(X[7].z), y4=__expf(X[7].w), y5=__expf(X[8].x);
            float y6=__expf(X[8].y), y7=__expf(X[8].z), y8=__expf(X[8].w);
            matvec(y0,y1,y2,y3,y4,y5,y6,y7,y8, p0,p1,p2,p3,p4,p5,p6,p7,p8);
            stepb(X[4].z,X[4].w, X[5].x,X[5].y,X[5].z,X[5].w, X[6].x,X[6].y,X[6].z);
            stepb(X[2].y,X[2].z,X[2].w, X[3].x,X[3].y,X[3].z,X[3].w, X[4].x,X[4].y);
            stepb(X[0].x,X[0].y,X[0].z,X[0].w, X[1].x,X[1].y,X[1].z,X[1].w, X[2].x);
            emit = lds_f(xb + (unsigned int)(P.x * 4))
                 + lds_f(xb + 36 + (unsigned int)(P.y * 4))
                 + lds_f(xb + 72 + (unsigned int)(P.z * 4))
                 + lds_f(xb + 108 + (unsigned int)(P.w * 4));
            tracc = s_tran[P.z * 9 + P.w] + s_tran[P.y * 9 + P.z] + s_tran[P.x * 9 + P.y];
            ptp = P.x;
        }

        #pragma unroll 1
        for (int g = 62; g >= 35; --g) {
            CP_WAIT(2); __syncwarp();
            issue(g - 3);
            bbody(g);
        }
        CP_WAIT(2); __syncwarp(); bbody(34);
        CP_WAIT(1); __syncwarp(); bbody(33);
        CP_WAIT(0); __syncwarp(); bbody(32);

        fin[frow][12]=p0; fin[frow][13]=p1; fin[frow][14]=p2; fin[frow][15]=p3;
        fin[frow][16]=p4; fin[frow][17]=p5; fin[frow][18]=p6; fin[frow][19]=p7;
        fin[frow][20]=p8;
        fin[frow][21] = C;
        fin[frow][22] = emit + tracc;
        fin[frow][23] = __int_as_float(ptp);
    }

    __syncthreads();

    if (dir == 0) {
        float dot = 0.f;
        #pragma unroll
        for (int i = 0; i < 9; ++i)
            dot = fmaf(fin[frow][i], fin[frow][12 + i], dot);
        float logZ = fin[frow][9] + fin[frow][21] + __logf(dot);
        int pa = __float_as_int(fin[frow][11]);
        int pb = __float_as_int(fin[frow][23]);
        float score = fin[frow][10] + fin[frow][22] + s_tran[pa * 9 + pb];
        out[b] = logZ - score;
    }
}

extern "C" void kernel_launch(void* const* d_in, const int* in_sizes, int n_in,
                              void* d_out, int out_size) {
    (void)in_sizes; (void)n_in; (void)out_size;
    const float* inputs = (const float*)d_in[0];
    const int*   path   = (const int*)d_in[1];
    const float* tran   = (const float*)d_in[2];
    const float* initv  = (const float*)d_in[3];
    float* out = (float*)d_out;

    cudaFuncSetAttribute(crf_fwd_kernel,
                         cudaFuncAttributeMaxDynamicSharedMemorySize, DYN_SMEM);
    crf_fwd_kernel<<<BB / 64, 128, DYN_SMEM>>>(inputs, path, tran, initv, out);
}